// round 11
// baseline (speedup 1.0000x reference)
#include <cuda_runtime.h>

#define FULLMASK 0xFFFFFFFFu
#define WARPS_PER_ROW 8
#define B_CONST 4096
#define T_CONST 8192

// Static scratch (allocation-free rule): packed obs bits + per-chunk seeds.
__device__ unsigned g_bits[(size_t)B_CONST * (T_CONST / 32)];          // 4 MB
__device__ int      g_scnt[B_CONST * WARPS_PER_ROW];                   // 128 KB
__device__ float    g_dseed[B_CONST * WARPS_PER_ROW];                  // 128 KB

// ---------------- Kernel 1: pure-read pass ----------------
// One 256-thread block per row. Each warp packs its 1024-element chunk into
// 32 uints (1 per lane), computes chunk count -> s_start scan, lgamma D seed.
__global__ void __launch_bounds__(32 * WARPS_PER_ROW)
bbm_pack_kernel(const float* __restrict__ obs,
                const float* __restrict__ alpha1,
                const float* __restrict__ beta1,
                const float* __restrict__ alpha2,
                const float* __restrict__ beta2,
                int B, int T)
{
    const int wid  = threadIdx.x >> 5;
    const int lane = threadIdx.x & 31;
    const int row  = blockIdx.x;

    const int chunk = T / WARPS_PER_ROW;   // 1024

    const float4* __restrict__ orow =
        reinterpret_cast<const float4*>(obs + (size_t)row * (size_t)T);

    __shared__ int smem_cnt[WARPS_PER_ROW];

    unsigned packed = 0;
    const int vbase = wid * (chunk >> 2) + lane;
    #pragma unroll
    for (int i = 0; i < 8; ++i) {
        const float4 v = __ldcs(orow + vbase + i * 32);
        unsigned nib = (unsigned)(v.x > 0.5f)
                     | ((unsigned)(v.y > 0.5f) << 1)
                     | ((unsigned)(v.z > 0.5f) << 2)
                     | ((unsigned)(v.w > 0.5f) << 3);
        packed |= nib << (4 * i);
    }
    const int warpcnt = __reduce_add_sync(FULLMASK, __popc(packed));
    if (lane == 0) smem_cnt[wid] = warpcnt;

    // store packed bits (coalesced: 128B per warp)
    g_bits[((size_t)row * WARPS_PER_ROW + wid) * 32 + lane] = packed;

    __syncthreads();

    if (lane == 0) {
        int s_start = 0;
        #pragma unroll
        for (int k = 0; k < WARPS_PER_ROW; ++k)
            if (k < wid) s_start += smem_cnt[k];

        float D = 0.0f;
        if (wid != 0) {
            const float a1c = __ldg(alpha1 + row);
            const float b1c = __ldg(beta1  + row);
            const float a2c = __ldg(alpha2 + row);
            const float b2c = __ldg(beta2  + row);
            const float ab1 = a1c + b1c;
            const float ab2 = a2c + b2c;
            const float tf = (float)(wid * chunk);
            const float sf = (float)s_start;
            const float ff = tf - sf;
            const float d2 = (lgammaf(a2c + sf) + lgammaf(b2c + ff) - lgammaf(ab2 + tf))
                           - (lgammaf(a2c) + lgammaf(b2c) - lgammaf(ab2));
            const float d1 = (lgammaf(a1c + sf) + lgammaf(b1c + ff) - lgammaf(ab1 + tf))
                           - (lgammaf(a1c) + lgammaf(b1c) - lgammaf(ab1));
            D = d2 - d1;
        }
        g_scnt[row * WARPS_PER_ROW + wid]  = s_start;
        g_dseed[row * WARPS_PER_ROW + wid] = D;
    }
}

// ---------------- Kernel 2: pure-write pass ----------------
// Identical math to the R10 phase 2; obs replaced by the 4B/lane packed word.
__global__ void __launch_bounds__(32 * WARPS_PER_ROW)
bbm_write_kernel(const float* __restrict__ alpha1,
                 const float* __restrict__ beta1,
                 const float* __restrict__ alpha2,
                 const float* __restrict__ beta2,
                 const float* __restrict__ mixw,
                 float* __restrict__ out,
                 int B, int T)
{
    const int wid  = threadIdx.x >> 5;
    const int lane = threadIdx.x & 31;
    const int row  = blockIdx.x;

    const unsigned ltmask = (lane == 0) ? 0u : (FULLMASK >> (32 - lane));

    const float a1c = __ldg(alpha1 + row);
    const float b1c = __ldg(beta1  + row);
    const float a2c = __ldg(alpha2 + row);
    const float b2c = __ldg(beta2  + row);
    const float ab1 = a1c + b1c;
    const float ab2 = a2c + b2c;
    const float w   = __ldg(mixw);
    const float omw = 1.0f - w;

    const int chunk = T / WARPS_PER_ROW;   // 1024

    const unsigned packed = g_bits[((size_t)row * WARPS_PER_ROW + wid) * 32 + lane];
    int   s_carry = g_scnt[row * WARPS_PER_ROW + wid];
    float D_carry = g_dseed[row * WARPS_PER_ROW + wid];

    const size_t NT = (size_t)B * (size_t)T;
    float* o_a1 = out + (size_t)row * (size_t)T;
    float* o_b1 = o_a1 + NT;
    float* o_a2 = o_b1 + NT;
    float* o_b2 = o_a2 + NT;
    float* o_pm = o_b2 + NT;

    #pragma unroll
    for (int it = 0; it < 8; ++it) {
        const unsigned nib = (packed >> (4 * it)) & 0xF;
        const int b0 = (nib)      & 1;
        const int b1 = (nib >> 1) & 1;
        const int b2 = (nib >> 2) & 1;
        const int b3 = (nib >> 3) & 1;

        const unsigned m0 = __ballot_sync(FULLMASK, b0);
        const unsigned m1 = __ballot_sync(FULLMASK, b1);
        const unsigned m2 = __ballot_sync(FULLMASK, b2);
        const unsigned m3 = __ballot_sync(FULLMASK, b3);
        const int s0 = s_carry + __popc(m0 & ltmask) + __popc(m1 & ltmask)
                               + __popc(m2 & ltmask) + __popc(m3 & ltmask);
        const int cntTot = __popc(m0) + __popc(m1) + __popc(m2) + __popc(m3);

        const int   t0  = wid * chunk + (it << 7) + (lane << 2);
        const float t0f = (float)t0;

        int bj[4] = {b0, b1, b2, b3};
        float sfv[4], num[4], den[4];
        int ss = s0;
        #pragma unroll
        for (int j = 0; j < 4; ++j) {
            const float tf = t0f + (float)j;
            const float sf = (float)ss;
            const float ff = tf - sf;
            sfv[j] = sf;
            const float xv = bj[j] ? sf  : ff;
            const float c2 = bj[j] ? a2c : b2c;
            const float c1 = bj[j] ? a1c : b1c;
            num[j] = (c2 + xv) * (ab1 + tf);
            den[j] = (c1 + xv) * (ab2 + tf);
            ss += bj[j];
        }
        float cnex[4], cdex[4];
        cnex[0] = 1.0f;             cdex[0] = 1.0f;
        cnex[1] = num[0];           cdex[1] = den[0];
        cnex[2] = cnex[1] * num[1]; cdex[2] = cdex[1] * den[1];
        cnex[3] = cnex[2] * num[2]; cdex[3] = cdex[2] * den[2];
        const float cnInc = cnex[3] * num[3];
        const float cdInc = cdex[3] * den[3];

        const float dacc = __logf(__fdividef(cnInc, cdInc));

        float finc = dacc;
        #pragma unroll
        for (int d = 1; d < 32; d <<= 1) {
            float n = __shfl_up_sync(FULLMASK, finc, d);
            if (lane >= d) finc += n;
        }
        const float Dbase = D_carry + (finc - dacc);
        const float Dtot  = __shfl_sync(FULLMASK, finc, 31);

        const float omwEb = omw * __expf(Dbase);

        float oa1[4], ob1[4], oa2[4], ob2[4], opm[4];
        #pragma unroll
        for (int j = 0; j < 4; ++j) {
            const float tf = t0f + (float)j;
            const float sf = sfv[j];
            const float ff = tf - sf;
            oa1[j] = a1c + sf;
            ob1[j] = b1c + ff;
            oa2[j] = a2c + sf;
            ob2[j] = b2c + ff;
            const float wn = w * cdex[j];
            opm[j] = __fdividef(wn, fmaf(omwEb, cnex[j], wn));
        }

        *reinterpret_cast<float4*>(o_a1 + t0) = make_float4(oa1[0], oa1[1], oa1[2], oa1[3]);
        *reinterpret_cast<float4*>(o_b1 + t0) = make_float4(ob1[0], ob1[1], ob1[2], ob1[3]);
        *reinterpret_cast<float4*>(o_a2 + t0) = make_float4(oa2[0], oa2[1], oa2[2], oa2[3]);
        *reinterpret_cast<float4*>(o_b2 + t0) = make_float4(ob2[0], ob2[1], ob2[2], ob2[3]);
        *reinterpret_cast<float4*>(o_pm + t0) = make_float4(opm[0], opm[1], opm[2], opm[3]);

        s_carry += cntTot;
        D_carry += Dtot;
    }
}

extern "C" void kernel_launch(void* const* d_in, const int* in_sizes, int n_in,
                              void* d_out, int out_size)
{
    const float* obs = (const float*)d_in[0];
    const float* a1  = (const float*)d_in[1];
    const float* b1  = (const float*)d_in[2];
    const float* a2  = (const float*)d_in[3];
    const float* b2  = (const float*)d_in[4];
    const float* mw  = (const float*)d_in[5];

    const int B = in_sizes[1];
    const int T = in_sizes[0] / B;

    dim3 block(32 * WARPS_PER_ROW);
    dim3 grid(B);
    bbm_pack_kernel<<<grid, block>>>(obs, a1, b1, a2, b2, B, T);
    bbm_write_kernel<<<grid, block>>>(a1, b1, a2, b2, mw, (float*)d_out, B, T);
}

// round 12
// speedup vs baseline: 1.0066x; 1.0066x over previous
#include <cuda_runtime.h>

#define FULLMASK 0xFFFFFFFFu
#define WARPS_PER_ROW 8
#define B_CONST 4096
#define T_CONST 8192

// Static scratch (allocation-free rule): packed obs bits + per-warp counts.
__device__ unsigned g_bits[(size_t)B_CONST * (T_CONST / 32)];   // 4 MB
__device__ int      g_cnt[B_CONST * WARPS_PER_ROW];             // 128 KB

// ---------------- Kernel 1: pure streaming pack ----------------
// No syncthreads, no lgamma, no block scan: read 1024 elems/warp, pack to
// 32 uints (1/lane), store per-warp population count. Free-running.
__global__ void __launch_bounds__(32 * WARPS_PER_ROW)
bbm_pack_kernel(const float* __restrict__ obs, int B, int T)
{
    const int wid  = threadIdx.x >> 5;
    const int lane = threadIdx.x & 31;
    const int row  = blockIdx.x;

    const int chunk = T / WARPS_PER_ROW;   // 1024

    const float4* __restrict__ orow =
        reinterpret_cast<const float4*>(obs + (size_t)row * (size_t)T);

    unsigned packed = 0;
    const int vbase = wid * (chunk >> 2) + lane;
    #pragma unroll
    for (int i = 0; i < 8; ++i) {
        const float4 v = __ldcs(orow + vbase + i * 32);
        unsigned nib = (unsigned)(v.x > 0.5f)
                     | ((unsigned)(v.y > 0.5f) << 1)
                     | ((unsigned)(v.z > 0.5f) << 2)
                     | ((unsigned)(v.w > 0.5f) << 3);
        packed |= nib << (4 * i);
    }
    g_bits[((size_t)row * WARPS_PER_ROW + wid) * 32 + lane] = packed;

    const int warpcnt = __reduce_add_sync(FULLMASK, __popc(packed));
    if (lane == 0) g_cnt[row * WARPS_PER_ROW + wid] = warpcnt;
}

// ---------------- Kernel 2: write pass (R10 math; bits/counts from scratch) ----------------
__global__ void __launch_bounds__(32 * WARPS_PER_ROW)
bbm_write_kernel(const float* __restrict__ alpha1,
                 const float* __restrict__ beta1,
                 const float* __restrict__ alpha2,
                 const float* __restrict__ beta2,
                 const float* __restrict__ mixw,
                 float* __restrict__ out,
                 int B, int T)
{
    const int wid  = threadIdx.x >> 5;
    const int lane = threadIdx.x & 31;
    const int row  = blockIdx.x;

    const unsigned ltmask = (lane == 0) ? 0u : (FULLMASK >> (32 - lane));

    const float a1c = __ldg(alpha1 + row);
    const float b1c = __ldg(beta1  + row);
    const float a2c = __ldg(alpha2 + row);
    const float b2c = __ldg(beta2  + row);
    const float ab1 = a1c + b1c;
    const float ab2 = a2c + b2c;
    const float w   = __ldg(mixw);
    const float omw = 1.0f - w;

    const int chunk = T / WARPS_PER_ROW;   // 1024

    // packed bits for this warp's chunk (L2-resident, written by K1)
    const unsigned packed = g_bits[((size_t)row * WARPS_PER_ROW + wid) * 32 + lane];

    // s_start from the per-warp counts of preceding chunks (8 ints, L2-hit)
    int s_start = 0;
    #pragma unroll
    for (int k = 0; k < WARPS_PER_ROW; ++k)
        if (k < wid) s_start += __ldg(g_cnt + row * WARPS_PER_ROW + k);

    // chunk D seed via lgamma closed form (overlaps with store stream startup)
    float D_carry = 0.0f;
    if (wid != 0) {
        const float tf = (float)(wid * chunk);
        const float sf = (float)s_start;
        const float ff = tf - sf;
        const float d2 = (lgammaf(a2c + sf) + lgammaf(b2c + ff) - lgammaf(ab2 + tf))
                       - (lgammaf(a2c) + lgammaf(b2c) - lgammaf(ab2));
        const float d1 = (lgammaf(a1c + sf) + lgammaf(b1c + ff) - lgammaf(ab1 + tf))
                       - (lgammaf(a1c) + lgammaf(b1c) - lgammaf(ab1));
        D_carry = d2 - d1;
    }
    int s_carry = s_start;

    const size_t NT = (size_t)B * (size_t)T;
    float* o_a1 = out + (size_t)row * (size_t)T;
    float* o_b1 = o_a1 + NT;
    float* o_a2 = o_b1 + NT;
    float* o_b2 = o_a2 + NT;
    float* o_pm = o_b2 + NT;

    #pragma unroll
    for (int it = 0; it < 8; ++it) {
        const unsigned nib = (packed >> (4 * it)) & 0xF;
        const int b0 = (nib)      & 1;
        const int b1 = (nib >> 1) & 1;
        const int b2 = (nib >> 2) & 1;
        const int b3 = (nib >> 3) & 1;

        const unsigned m0 = __ballot_sync(FULLMASK, b0);
        const unsigned m1 = __ballot_sync(FULLMASK, b1);
        const unsigned m2 = __ballot_sync(FULLMASK, b2);
        const unsigned m3 = __ballot_sync(FULLMASK, b3);
        const int s0 = s_carry + __popc(m0 & ltmask) + __popc(m1 & ltmask)
                               + __popc(m2 & ltmask) + __popc(m3 & ltmask);
        const int cntTot = __popc(m0) + __popc(m1) + __popc(m2) + __popc(m3);

        const int   t0  = wid * chunk + (it << 7) + (lane << 2);
        const float t0f = (float)t0;

        int bj[4] = {b0, b1, b2, b3};
        float sfv[4], num[4], den[4];
        int ss = s0;
        #pragma unroll
        for (int j = 0; j < 4; ++j) {
            const float tf = t0f + (float)j;
            const float sf = (float)ss;
            const float ff = tf - sf;
            sfv[j] = sf;
            const float xv = bj[j] ? sf  : ff;
            const float c2 = bj[j] ? a2c : b2c;
            const float c1 = bj[j] ? a1c : b1c;
            num[j] = (c2 + xv) * (ab1 + tf);
            den[j] = (c1 + xv) * (ab2 + tf);
            ss += bj[j];
        }
        float cnex[4], cdex[4];
        cnex[0] = 1.0f;             cdex[0] = 1.0f;
        cnex[1] = num[0];           cdex[1] = den[0];
        cnex[2] = cnex[1] * num[1]; cdex[2] = cdex[1] * den[1];
        cnex[3] = cnex[2] * num[2]; cdex[3] = cdex[2] * den[2];
        const float cnInc = cnex[3] * num[3];
        const float cdInc = cdex[3] * den[3];

        const float dacc = __logf(__fdividef(cnInc, cdInc));

        float finc = dacc;
        #pragma unroll
        for (int d = 1; d < 32; d <<= 1) {
            float n = __shfl_up_sync(FULLMASK, finc, d);
            if (lane >= d) finc += n;
        }
        const float Dbase = D_carry + (finc - dacc);
        const float Dtot  = __shfl_sync(FULLMASK, finc, 31);

        const float omwEb = omw * __expf(Dbase);

        float oa1[4], ob1[4], oa2[4], ob2[4], opm[4];
        #pragma unroll
        for (int j = 0; j < 4; ++j) {
            const float tf = t0f + (float)j;
            const float sf = sfv[j];
            const float ff = tf - sf;
            oa1[j] = a1c + sf;
            ob1[j] = b1c + ff;
            oa2[j] = a2c + sf;
            ob2[j] = b2c + ff;
            const float wn = w * cdex[j];
            opm[j] = __fdividef(wn, fmaf(omwEb, cnex[j], wn));
        }

        *reinterpret_cast<float4*>(o_a1 + t0) = make_float4(oa1[0], oa1[1], oa1[2], oa1[3]);
        *reinterpret_cast<float4*>(o_b1 + t0) = make_float4(ob1[0], ob1[1], ob1[2], ob1[3]);
        *reinterpret_cast<float4*>(o_a2 + t0) = make_float4(oa2[0], oa2[1], oa2[2], oa2[3]);
        *reinterpret_cast<float4*>(o_b2 + t0) = make_float4(ob2[0], ob2[1], ob2[2], ob2[3]);
        *reinterpret_cast<float4*>(o_pm + t0) = make_float4(opm[0], opm[1], opm[2], opm[3]);

        s_carry += cntTot;
        D_carry += Dtot;
    }
}

extern "C" void kernel_launch(void* const* d_in, const int* in_sizes, int n_in,
                              void* d_out, int out_size)
{
    const float* obs = (const float*)d_in[0];
    const float* a1  = (const float*)d_in[1];
    const float* b1  = (const float*)d_in[2];
    const float* a2  = (const float*)d_in[3];
    const float* b2  = (const float*)d_in[4];
    const float* mw  = (const float*)d_in[5];

    const int B = in_sizes[1];
    const int T = in_sizes[0] / B;

    dim3 block(32 * WARPS_PER_ROW);
    dim3 grid(B);
    bbm_pack_kernel<<<grid, block>>>(obs, B, T);
    bbm_write_kernel<<<grid, block>>>(a1, b1, a2, b2, mw, (float*)d_out, B, T);
}

// round 13
// speedup vs baseline: 1.0510x; 1.0441x over previous
#include <cuda_runtime.h>

#define FULLMASK 0xFFFFFFFFu
#define WARPS_PER_ROW 8

// FINAL (best measured: 126.0us, rel_err 1.9e-7, DRAM 77% / 6.1 TB/s ncu,
// 6.6 TB/s effective aggregate = measured chip ceiling for this mix).
//
// One 256-thread block per row; each warp owns a 1024-element chunk.
// Phase 1: packed read (32 obs bits/lane) + block count scan -> s_start;
//          chunk D_base via lgamma closed form (betaln telescoped).
// Phase 2: 8 sequential sub-iterations (128 elems each), small live state:
//          ballot lane-prefix, FMA-pipe exclusive cumprods of likelihood
//          ratio factors, 1 log + 1 exp per lane per sub-iter, 1 fast-div
//          per element, float4 coalesced stores to all 5 output planes.
//
// Design history (all measured worse): forced reg caps (spills/remat),
// 8-way ILP-wide restructure (170 regs -> occ 11%), smem two-pass (phase-
// locked bursty DRAM), streaming cache hints (neutral), 2-kernel read/write
// split (launch + short-kernel overhead > turnaround savings).
__global__ void __launch_bounds__(32 * WARPS_PER_ROW)
bbm_kernel(const float* __restrict__ obs,
           const float* __restrict__ alpha1,
           const float* __restrict__ beta1,
           const float* __restrict__ alpha2,
           const float* __restrict__ beta2,
           const float* __restrict__ mixw,
           float* __restrict__ out,
           int B, int T)
{
    const int wid  = threadIdx.x >> 5;
    const int lane = threadIdx.x & 31;
    const int row  = blockIdx.x;

    const unsigned ltmask = (lane == 0) ? 0u : (FULLMASK >> (32 - lane));

    const float a1c = __ldg(alpha1 + row);
    const float b1c = __ldg(beta1  + row);
    const float a2c = __ldg(alpha2 + row);
    const float b2c = __ldg(beta2  + row);
    const float ab1 = a1c + b1c;
    const float ab2 = a2c + b2c;
    const float w   = __ldg(mixw);
    const float omw = 1.0f - w;

    const int chunk    = T / WARPS_PER_ROW;   // 1024
    const int subiters = chunk >> 7;          // 8

    const float4* __restrict__ orow =
        reinterpret_cast<const float4*>(obs + (size_t)row * (size_t)T);

    const size_t NT = (size_t)B * (size_t)T;
    float* o_a1 = out + (size_t)row * (size_t)T;
    float* o_b1 = o_a1 + NT;
    float* o_a2 = o_b1 + NT;
    float* o_b2 = o_a2 + NT;
    float* o_pm = o_b2 + NT;

    __shared__ int smem_cnt[WARPS_PER_ROW];

    // ---------- Phase 1: load chunk, pack bits, count ----------
    unsigned packed = 0;
    const int vbase = wid * (chunk >> 2) + lane;
    #pragma unroll
    for (int i = 0; i < 8; ++i) {
        const float4 v = orow[vbase + i * 32];
        unsigned nib = (unsigned)(v.x > 0.5f)
                     | ((unsigned)(v.y > 0.5f) << 1)
                     | ((unsigned)(v.z > 0.5f) << 2)
                     | ((unsigned)(v.w > 0.5f) << 3);
        packed |= nib << (4 * i);
    }
    const int warpcnt = __reduce_add_sync(FULLMASK, __popc(packed));
    if (lane == 0) smem_cnt[wid] = warpcnt;
    __syncthreads();

    int s_start = 0;
    #pragma unroll
    for (int k = 0; k < WARPS_PER_ROW; ++k)
        if (k < wid) s_start += smem_cnt[k];

    // ---------- D_base for this chunk via lgamma closed form ----------
    // D(s,t) = [lgG(a2+s)+lgG(b2+f)-lgG(ab2+t)] - [same for prior 1] - D(0,0)
    float D_carry = 0.0f;
    if (wid != 0) {
        const float tf = (float)(wid * chunk);
        const float sf = (float)s_start;
        const float ff = tf - sf;
        const float d2 = (lgammaf(a2c + sf) + lgammaf(b2c + ff) - lgammaf(ab2 + tf))
                       - (lgammaf(a2c) + lgammaf(b2c) - lgammaf(ab2));
        const float d1 = (lgammaf(a1c + sf) + lgammaf(b1c + ff) - lgammaf(ab1 + tf))
                       - (lgammaf(a1c) + lgammaf(b1c) - lgammaf(ab1));
        D_carry = d2 - d1;
    }
    int s_carry = s_start;

    // ---------- Phase 2: local recurrence over 8 sub-iterations ----------
    for (int it = 0; it < subiters; ++it) {
        const unsigned nib = (packed >> (4 * it)) & 0xF;
        const int b0 = (nib)      & 1;
        const int b1 = (nib >> 1) & 1;
        const int b2 = (nib >> 2) & 1;
        const int b3 = (nib >> 3) & 1;

        const unsigned m0 = __ballot_sync(FULLMASK, b0);
        const unsigned m1 = __ballot_sync(FULLMASK, b1);
        const unsigned m2 = __ballot_sync(FULLMASK, b2);
        const unsigned m3 = __ballot_sync(FULLMASK, b3);
        const int s0 = s_carry + __popc(m0 & ltmask) + __popc(m1 & ltmask)
                               + __popc(m2 & ltmask) + __popc(m3 & ltmask);
        const int cntTot = __popc(m0) + __popc(m1) + __popc(m2) + __popc(m3);

        const int   t0  = wid * chunk + (it << 7) + (lane << 2);
        const float t0f = (float)t0;

        // per-element ratio factors; exclusive cumulative products
        int bj[4] = {b0, b1, b2, b3};
        float sfv[4], num[4], den[4];
        int ss = s0;
        #pragma unroll
        for (int j = 0; j < 4; ++j) {
            const float tf = t0f + (float)j;
            const float sf = (float)ss;
            const float ff = tf - sf;          // exact: small integers in fp32
            sfv[j] = sf;
            const float xv = bj[j] ? sf  : ff;
            const float c2 = bj[j] ? a2c : b2c;
            const float c1 = bj[j] ? a1c : b1c;
            num[j] = (c2 + xv) * (ab1 + tf);
            den[j] = (c1 + xv) * (ab2 + tf);
            ss += bj[j];
        }
        float cnex[4], cdex[4];
        cnex[0] = 1.0f;             cdex[0] = 1.0f;
        cnex[1] = num[0];           cdex[1] = den[0];
        cnex[2] = cnex[1] * num[1]; cdex[2] = cdex[1] * den[1];
        cnex[3] = cnex[2] * num[2]; cdex[3] = cdex[2] * den[2];
        const float cnInc = cnex[3] * num[3];
        const float cdInc = cdex[3] * den[3];

        // one log per lane: this lane's total delta-D
        const float dacc = __logf(__fdividef(cnInc, cdInc));

        float finc = dacc;
        #pragma unroll
        for (int d = 1; d < 32; d <<= 1) {
            float n = __shfl_up_sync(FULLMASK, finc, d);
            if (lane >= d) finc += n;
        }
        const float Dbase = D_carry + (finc - dacc);   // exclusive prefix
        const float Dtot  = __shfl_sync(FULLMASK, finc, 31);

        const float omwEb = omw * __expf(Dbase);

        // outputs: a/b planes exact; pm = w*cd / (w*cd + (1-w)*e^Dbase*cn)
        float oa1[4], ob1[4], oa2[4], ob2[4], opm[4];
        #pragma unroll
        for (int j = 0; j < 4; ++j) {
            const float tf = t0f + (float)j;
            const float sf = sfv[j];
            const float ff = tf - sf;
            oa1[j] = a1c + sf;
            ob1[j] = b1c + ff;
            oa2[j] = a2c + sf;
            ob2[j] = b2c + ff;
            const float wn = w * cdex[j];
            opm[j] = __fdividef(wn, fmaf(omwEb, cnex[j], wn));
        }

        *reinterpret_cast<float4*>(o_a1 + t0) = make_float4(oa1[0], oa1[1], oa1[2], oa1[3]);
        *reinterpret_cast<float4*>(o_b1 + t0) = make_float4(ob1[0], ob1[1], ob1[2], ob1[3]);
        *reinterpret_cast<float4*>(o_a2 + t0) = make_float4(oa2[0], oa2[1], oa2[2], oa2[3]);
        *reinterpret_cast<float4*>(o_b2 + t0) = make_float4(ob2[0], ob2[1], ob2[2], ob2[3]);
        *reinterpret_cast<float4*>(o_pm + t0) = make_float4(opm[0], opm[1], opm[2], opm[3]);

        s_carry += cntTot;
        D_carry += Dtot;
    }
}

extern "C" void kernel_launch(void* const* d_in, const int* in_sizes, int n_in,
                              void* d_out, int out_size)
{
    const float* obs = (const float*)d_in[0];
    const float* a1  = (const float*)d_in[1];
    const float* b1  = (const float*)d_in[2];
    const float* a2  = (const float*)d_in[3];
    const float* b2  = (const float*)d_in[4];
    const float* mw  = (const float*)d_in[5];

    const int B = in_sizes[1];
    const int T = in_sizes[0] / B;

    dim3 block(32 * WARPS_PER_ROW);
    dim3 grid(B);
    bbm_kernel<<<grid, block>>>(obs, a1, b1, a2, b2, mw, (float*)d_out, B, T);
}